// round 2
// baseline (speedup 1.0000x reference)
#include <cuda_runtime.h>
#include <cuda_bf16.h>
#include <cstdint>

// Problem dims (fixed by the benchmark)
#define BB 4
#define TT 4096
#define HH 2048
#define LL 4
#define MROWS (BB * TT)        // 16384
#define N3H (3 * HH)           // 6144

// ---------------- scratch (no allocation allowed -> __device__ globals) ----
__device__ float g_BCx[(size_t)MROWS * N3H];  // 16384 x 6144  (384 MB)
__device__ float g_y[(size_t)MROWS * HH];     // 16384 x 2048  (128 MB)

// ---------------- SGEMM: C = A(MxK) @ B(KxN), all row-major, fp32 ----------
// 128x128 block tile, BK=16, 256 threads, 8x8 per-thread microtile.
#define BM 128
#define BN 128
#define BK 16

__device__ __forceinline__ void sgemm_body(
    const float* __restrict__ A, const float* __restrict__ B,
    float* __restrict__ C, int N, int K)
{
    __shared__ float As[BK][BM + 4];   // padded to soften store conflicts
    __shared__ float Bs[BK][BN];

    const int tid = threadIdx.x;
    const int tx = tid & 15;          // 0..15  -> N direction
    const int ty = tid >> 4;          // 0..15  -> M direction
    const int block_m = blockIdx.y * BM;
    const int block_n = blockIdx.x * BN;

    // A tile loaders: 128 rows x 16 cols = 512 float4; 2 per thread
    const int a_row  = tid >> 2;      // 0..63
    const int a_col4 = (tid & 3) * 4; // 0,4,8,12
    // B tile loaders: 16 rows x 128 cols = 512 float4; 2 per thread
    const int b_row  = tid >> 5;      // 0..7
    const int b_col4 = (tid & 31) * 4;

    const float* Abase = A + (size_t)(block_m + a_row) * K + a_col4;
    const float* Bbase = B + (size_t)b_row * N + block_n + b_col4;

    float acc[8][8];
    #pragma unroll
    for (int i = 0; i < 8; ++i)
        #pragma unroll
        for (int j = 0; j < 8; ++j) acc[i][j] = 0.f;

    for (int k0 = 0; k0 < K; k0 += BK) {
        // --- load A tile (transposed into smem) ---
        float4 a0 = *(const float4*)(Abase + k0);
        float4 a1 = *(const float4*)(Abase + k0 + (size_t)64 * K);
        As[a_col4 + 0][a_row] = a0.x;
        As[a_col4 + 1][a_row] = a0.y;
        As[a_col4 + 2][a_row] = a0.z;
        As[a_col4 + 3][a_row] = a0.w;
        As[a_col4 + 0][a_row + 64] = a1.x;
        As[a_col4 + 1][a_row + 64] = a1.y;
        As[a_col4 + 2][a_row + 64] = a1.z;
        As[a_col4 + 3][a_row + 64] = a1.w;
        // --- load B tile ---
        const float* Bp = Bbase + (size_t)k0 * N;
        *(float4*)&Bs[b_row][b_col4]     = *(const float4*)(Bp);
        *(float4*)&Bs[b_row + 8][b_col4] = *(const float4*)(Bp + (size_t)8 * N);
        __syncthreads();

        #pragma unroll
        for (int k = 0; k < BK; ++k) {
            float ar[8], br[8];
            #pragma unroll
            for (int i = 0; i < 8; ++i) ar[i] = As[k][ty * 8 + i];
            #pragma unroll
            for (int j = 0; j < 8; ++j) br[j] = Bs[k][tx * 8 + j];
            #pragma unroll
            for (int i = 0; i < 8; ++i)
                #pragma unroll
                for (int j = 0; j < 8; ++j)
                    acc[i][j] += ar[i] * br[j];
        }
        __syncthreads();
    }

    // --- epilogue: vectorized stores ---
    #pragma unroll
    for (int i = 0; i < 8; ++i) {
        float* Cp = C + (size_t)(block_m + ty * 8 + i) * N + block_n + tx * 8;
        #pragma unroll
        for (int j = 0; j < 8; j += 4) {
            float4 v;
            v.x = acc[i][j + 0]; v.y = acc[i][j + 1];
            v.z = acc[i][j + 2]; v.w = acc[i][j + 3];
            *(float4*)(Cp + j) = v;
        }
    }
}

__global__ __launch_bounds__(256)
void gemm1_kernel(const float* __restrict__ x, const float* __restrict__ W_in)
{
    sgemm_body(x, W_in, g_BCx, N3H, HH);
}

__global__ __launch_bounds__(256)
void gemm2_kernel(const float* __restrict__ W_out, float* __restrict__ out)
{
    sgemm_body(g_y, W_out, out, HH, HH);
}

// ---------------- fused gate + mask + causal depthwise conv + Cg gate ------
// y[b,t,h] = Cg[b,t,h] * sum_k conv_w[h,k] * Bx[b, t+k-(L-1), h]
// Bx[b,t,h] = mask[b,t] ? Bg[b,t,h]*xg[b,t,h] : 0
// Layout of g_BCx row (b*T+t): [Bg(0:H) | Cg(H:2H) | xg(2H:3H)]
// NOTE: mask arrives as int32 (bool widened by the harness).
#define CONV_CHUNK 128

__global__ __launch_bounds__(256)
void conv_kernel(const int* __restrict__ mask,
                 const float* __restrict__ conv_w)
{
    const int h  = blockIdx.x * 256 + threadIdx.x;    // 0..2047
    const int b  = blockIdx.z;
    const int t0 = blockIdx.y * CONV_CHUNK;

    const float cw0 = conv_w[h * LL + 0];
    const float cw1 = conv_w[h * LL + 1];
    const float cw2 = conv_w[h * LL + 2];
    const float cw3 = conv_w[h * LL + 3];

    // rolling window: p1 = Bx(t-1), p2 = Bx(t-2), p3 = Bx(t-3)
    float p1 = 0.f, p2 = 0.f, p3 = 0.f;
    #pragma unroll
    for (int d = 3; d >= 1; --d) {
        int t = t0 - d;
        float bx = 0.f;
        if (t >= 0 && mask[b * TT + t] != 0) {
            size_t base = ((size_t)(b * TT + t)) * N3H;
            bx = g_BCx[base + h] * g_BCx[base + 2 * HH + h];
        }
        p3 = p2; p2 = p1; p1 = bx;
    }

    for (int t = t0; t < t0 + CONV_CHUNK; ++t) {
        size_t base = ((size_t)(b * TT + t)) * N3H;
        float Bg = g_BCx[base + h];
        float Cg = g_BCx[base + HH + h];
        float xg = g_BCx[base + 2 * HH + h];
        float bx = (mask[b * TT + t] != 0) ? (Bg * xg) : 0.f;
        float conv = cw0 * p3 + cw1 * p2 + cw2 * p1 + cw3 * bx;
        g_y[((size_t)(b * TT + t)) * HH + h] = Cg * conv;
        p3 = p2; p2 = p1; p1 = bx;
    }
}

// ---------------- launch -----------------------------------------------------
extern "C" void kernel_launch(void* const* d_in, const int* in_sizes, int n_in,
                              void* d_out, int out_size)
{
    const float* x      = (const float*)d_in[0];
    const int*   mask   = (const int*)d_in[1];    // bool widened to int32
    const float* W_in   = (const float*)d_in[2];
    const float* conv_w = (const float*)d_in[3];
    const float* W_out  = (const float*)d_in[4];
    float*       out    = (float*)d_out;

    // GEMM1: (16384 x 2048) @ (2048 x 6144) -> g_BCx
    {
        dim3 grid(N3H / BN, MROWS / BM);   // 48 x 128
        gemm1_kernel<<<grid, 256>>>(x, W_in);
    }
    // gate + conv + gate -> g_y
    {
        dim3 grid(HH / 256, TT / CONV_CHUNK, BB);  // 8 x 32 x 4
        conv_kernel<<<grid, 256>>>(mask, conv_w);
    }
    // GEMM2: (16384 x 2048) @ (2048 x 2048) -> out
    {
        dim3 grid(HH / BN, MROWS / BM);    // 16 x 128
        gemm2_kernel<<<grid, 256>>>(W_out, out);
    }
}

// round 6
// speedup vs baseline: 2.0474x; 2.0474x over previous
#include <cuda_runtime.h>
#include <cuda_fp16.h>
#include <cstdint>

// Problem dims (fixed)
#define BB 4
#define TT 4096
#define HH 2048
#define LL 4
#define MROWS 16384
#define N3H 6144
#define KDIM 2048

// GEMM tiling: CTA 128x128, BK=16, 2-stage cp.async, 8 warps (4x2), warp 32x64
#define BKT 16
#define NITER (KDIM / BKT)          // 128
#define TILE_B 4096                 // 128 rows x 32 bytes
#define STAGE_B (4 * TILE_B)        // Ah, Al, Bh, Bl = 16 KB

// ---------------- scratch (__device__ globals; referenced ONLY in device code)
__device__ float  g_BCx[(size_t)MROWS * N3H];     // 384 MB fp32
__device__ __half g_xh[(size_t)MROWS * HH];
__device__ __half g_xl[(size_t)MROWS * HH];
__device__ __half g_yh[(size_t)MROWS * HH];
__device__ __half g_yl[(size_t)MROWS * HH];
__device__ __half g_Wint_h[(size_t)N3H * HH];     // W_in^T  [6144][2048]
__device__ __half g_Wint_l[(size_t)N3H * HH];
__device__ __half g_Wot_h[(size_t)HH * HH];       // W_out^T [2048][2048]
__device__ __half g_Wot_l[(size_t)HH * HH];

// ---------------- PTX helpers (plain sm_103-safe) ----------------------------
__device__ __forceinline__ uint32_t smem_u32(const void* p) {
    uint32_t a;
    asm("{ .reg .u64 t; cvta.to.shared.u64 t, %1; cvt.u32.u64 %0, t; }" : "=r"(a) : "l"(p));
    return a;
}
// swizzle for 32B-row tiles: spread 16B chunks so 8 ldmatrix rows hit 8 slots
#define SWZ32(off) ((off) ^ (((off) >> 3) & 0x10))

#define CP_ASYNC16(dst, src) \
    asm volatile("cp.async.cg.shared.global [%0], [%1], 16;" :: "r"(dst), "l"(src))
#define CP_ASYNC_COMMIT() asm volatile("cp.async.commit_group;")
#define CP_ASYNC_WAIT(n)  asm volatile("cp.async.wait_group %0;" :: "n"(n))

#define LDSM_X4(r0, r1, r2, r3, addr) \
    asm volatile("ldmatrix.sync.aligned.m8n8.x4.shared.b16 {%0,%1,%2,%3}, [%4];" \
        : "=r"(r0), "=r"(r1), "=r"(r2), "=r"(r3) : "r"(addr))

#define MMA16816(d, a, b0, b1) \
    asm volatile("mma.sync.aligned.m16n8k16.row.col.f32.f16.f16.f32 " \
        "{%0,%1,%2,%3}, {%4,%5,%6,%7}, {%8,%9}, {%0,%1,%2,%3};" \
        : "+f"((d)[0]), "+f"((d)[1]), "+f"((d)[2]), "+f"((d)[3]) \
        : "r"((a)[0]), "r"((a)[1]), "r"((a)[2]), "r"((a)[3]), "r"(b0), "r"(b1))

// ---------------- prep kernels ----------------------------------------------
__global__ __launch_bounds__(256)
void split_x_kernel(const float* __restrict__ x)
{
    size_t i = ((size_t)blockIdx.x * 256 + threadIdx.x) * 4;
    float4 v = *(const float4*)(x + i);
    float f[4] = {v.x, v.y, v.z, v.w};
    __half h[4], l[4];
    #pragma unroll
    for (int j = 0; j < 4; ++j) {
        h[j] = __float2half(f[j]);
        l[j] = __float2half(f[j] - __half2float(h[j]));
    }
    *(uint2*)(g_xh + i) = *(uint2*)h;
    *(uint2*)(g_xl + i) = *(uint2*)l;
}

// transpose + split: in fp32 [R][C] -> (device-global) oh/ol fp16 [C][R]
// wsel: 0 -> g_Wint_h/l,  1 -> g_Wot_h/l
__global__ __launch_bounds__(256)
void transpose_split_kernel(const float* __restrict__ in, int wsel, int R, int C)
{
    __half* __restrict__ oh = wsel ? g_Wot_h : g_Wint_h;
    __half* __restrict__ ol = wsel ? g_Wot_l : g_Wint_l;

    __shared__ float tile[32][33];
    int tx = threadIdx.x, ty = threadIdx.y;
    int x = blockIdx.x * 32 + tx;
    int y0 = blockIdx.y * 32;
    #pragma unroll
    for (int j = ty; j < 32; j += 8)
        tile[j][tx] = in[(size_t)(y0 + j) * C + x];
    __syncthreads();
    int ox = y0 + tx;
    int oy0 = blockIdx.x * 32;
    #pragma unroll
    for (int j = ty; j < 32; j += 8) {
        float v = tile[tx][j];
        __half h = __float2half(v);
        __half l = __float2half(v - __half2float(h));
        size_t o = (size_t)(oy0 + j) * R + ox;
        oh[o] = h; ol[o] = l;
    }
}

// ---------------- split-precision fp16 mma.sync GEMM ------------------------
__device__ __forceinline__ void load_stage16(
    char* sbase, int k0, int bm, int bn,
    const __half* __restrict__ Ah, const __half* __restrict__ Al,
    const __half* __restrict__ Bh, const __half* __restrict__ Bl, int tid)
{
    const __half* srcs[4] = {Ah, Al, Bh, Bl};
    const int r = tid >> 1;          // row 0..127
    const int ch = tid & 1;          // 16B chunk 0..1
    #pragma unroll
    for (int sub = 0; sub < 4; ++sub) {
        const int rowbase = (sub < 2) ? bm : bn;
        uint32_t dst = smem_u32(sbase + sub * TILE_B);
        const __half* src = srcs[sub] + (size_t)(rowbase + r) * KDIM + k0 + ch * 8;
        CP_ASYNC16(dst + SWZ32(r * 32 + ch * 16), src);
    }
    CP_ASYNC_COMMIT();
}

// gsel: 0 -> A=g_xh/g_xl, B=g_Wint_*, C=g_BCx (Cw=N3H)
//       1 -> A=g_yh/g_yl, B=g_Wot_*,  C=Cout  (Cw=HH)
__global__ __launch_bounds__(256, 1)
void gemm_mma_kernel(int gsel, float* __restrict__ Cout)
{
    const __half* __restrict__ Ah = gsel ? g_yh : g_xh;
    const __half* __restrict__ Al = gsel ? g_yl : g_xl;
    const __half* __restrict__ Bh = gsel ? g_Wot_h : g_Wint_h;
    const __half* __restrict__ Bl = gsel ? g_Wot_l : g_Wint_l;
    float* __restrict__ C  = gsel ? Cout : g_BCx;
    const int Cw = gsel ? HH : N3H;

    __shared__ __align__(1024) char smem[2 * STAGE_B];   // 32 KB static
    const int tid = threadIdx.x;
    const int wid = tid >> 5;
    const int lid = tid & 31;
    const int wm = wid & 3;           // 4 warps in M -> 32 rows each
    const int wn = wid >> 2;          // 2 warps in N -> 64 cols each
    const int bm = blockIdx.y * 128;
    const int bn = blockIdx.x * 128;

    float acc[2][8][4];
    #pragma unroll
    for (int t = 0; t < 2; ++t)
        #pragma unroll
        for (int j = 0; j < 8; ++j)
            #pragma unroll
            for (int e = 0; e < 4; ++e) acc[t][j][e] = 0.f;

    // ldmatrix lane address components (tile-local)
    const int a_row = (lid & 15);
    const int a_kb  = (lid & 16) ? 16 : 0;
    const int b_row = (lid & 7) + ((lid & 16) ? 8 : 0);
    const int b_kb  = (lid & 8) ? 16 : 0;

    // prologue: 2 stages in flight
    load_stage16(smem,           0,   bm, bn, Ah, Al, Bh, Bl, tid);
    load_stage16(smem + STAGE_B, BKT, bm, bn, Ah, Al, Bh, Bl, tid);

    for (int i = 0; i < NITER; ++i) {
        if (i + 2 < NITER) { CP_ASYNC_WAIT(1); } else { CP_ASYNC_WAIT(0); }
        __syncthreads();

        char* sbase = smem + (i & 1) * STAGE_B;
        const uint32_t tAh = smem_u32(sbase);
        const uint32_t tAl = tAh + TILE_B;
        const uint32_t tBh = tAh + 2 * TILE_B;
        const uint32_t tBl = tAh + 3 * TILE_B;

        uint32_t ah[2][4], al[2][4], bh[4][4], bl[4][4];
        #pragma unroll
        for (int t = 0; t < 2; ++t) {
            int row = wm * 32 + t * 16 + a_row;
            LDSM_X4(ah[t][0], ah[t][1], ah[t][2], ah[t][3], tAh + SWZ32(row * 32 + a_kb));
            LDSM_X4(al[t][0], al[t][1], al[t][2], al[t][3], tAl + SWZ32(row * 32 + a_kb));
        }
        #pragma unroll
        for (int g = 0; g < 4; ++g) {
            int row = wn * 64 + g * 16 + b_row;
            LDSM_X4(bh[g][0], bh[g][1], bh[g][2], bh[g][3], tBh + SWZ32(row * 32 + b_kb));
            LDSM_X4(bl[g][0], bl[g][1], bl[g][2], bl[g][3], tBl + SWZ32(row * 32 + b_kb));
        }
        #pragma unroll
        for (int t = 0; t < 2; ++t)
            #pragma unroll
            for (int g = 0; g < 4; ++g) {
                MMA16816(acc[t][2 * g],     ah[t], bh[g][0], bh[g][1]);
                MMA16816(acc[t][2 * g + 1], ah[t], bh[g][2], bh[g][3]);
                MMA16816(acc[t][2 * g],     ah[t], bl[g][0], bl[g][1]);
                MMA16816(acc[t][2 * g + 1], ah[t], bl[g][2], bl[g][3]);
                MMA16816(acc[t][2 * g],     al[t], bh[g][0], bh[g][1]);
                MMA16816(acc[t][2 * g + 1], al[t], bh[g][2], bh[g][3]);
            }
        __syncthreads();
        if (i + 2 < NITER)
            load_stage16(smem + (i & 1) * STAGE_B, (i + 2) * BKT, bm, bn, Ah, Al, Bh, Bl, tid);
    }

    // epilogue: fp32 accum -> C
    const int r0 = bm + wm * 32 + (lid >> 2);
    const int cb = bn + wn * 64 + (lid & 3) * 2;
    #pragma unroll
    for (int t = 0; t < 2; ++t)
        #pragma unroll
        for (int j = 0; j < 8; ++j) {
            float2 v0 = make_float2(acc[t][j][0], acc[t][j][1]);
            float2 v1 = make_float2(acc[t][j][2], acc[t][j][3]);
            *(float2*)(C + (size_t)(r0 + t * 16)     * Cw + cb + j * 8) = v0;
            *(float2*)(C + (size_t)(r0 + t * 16 + 8) * Cw + cb + j * 8) = v1;
        }
}

// ---------------- fused gate + mask + causal conv + Cg gate -----------------
#define CONV_CHUNK 128

__global__ __launch_bounds__(256)
void conv_kernel(const int* __restrict__ mask, const float* __restrict__ conv_w)
{
    const int h  = blockIdx.x * 256 + threadIdx.x;
    const int b  = blockIdx.z;
    const int t0 = blockIdx.y * CONV_CHUNK;

    const float cw0 = conv_w[h * LL + 0];
    const float cw1 = conv_w[h * LL + 1];
    const float cw2 = conv_w[h * LL + 2];
    const float cw3 = conv_w[h * LL + 3];

    float p1 = 0.f, p2 = 0.f, p3 = 0.f;
    #pragma unroll
    for (int d = 3; d >= 1; --d) {
        int t = t0 - d;
        float bx = 0.f;
        if (t >= 0 && mask[b * TT + t] != 0) {
            size_t base = ((size_t)(b * TT + t)) * N3H;
            bx = g_BCx[base + h] * g_BCx[base + 2 * HH + h];
        }
        p3 = p2; p2 = p1; p1 = bx;
    }

    for (int t = t0; t < t0 + CONV_CHUNK; ++t) {
        size_t base = ((size_t)(b * TT + t)) * N3H;
        float Bg = g_BCx[base + h];
        float Cg = g_BCx[base + HH + h];
        float xg = g_BCx[base + 2 * HH + h];
        float bx = (mask[b * TT + t] != 0) ? (Bg * xg) : 0.f;
        float conv = cw0 * p3 + cw1 * p2 + cw2 * p1 + cw3 * bx;
        float y = Cg * conv;
        size_t o = ((size_t)(b * TT + t)) * HH + h;
        __half hh = __float2half(y);
        g_yh[o] = hh;
        g_yl[o] = __float2half(y - __half2float(hh));
        p3 = p2; p2 = p1; p1 = bx;
    }
}

// ---------------- launch -----------------------------------------------------
extern "C" void kernel_launch(void* const* d_in, const int* in_sizes, int n_in,
                              void* d_out, int out_size)
{
    const float* x      = (const float*)d_in[0];
    const int*   mask   = (const int*)d_in[1];    // bool widened to int32
    const float* W_in   = (const float*)d_in[2];
    const float* conv_w = (const float*)d_in[3];
    const float* W_out  = (const float*)d_in[4];
    float*       out    = (float*)d_out;

    // prep: split x, transpose+split weights (globals selected device-side)
    split_x_kernel<<<(size_t)MROWS * HH / (256 * 4), 256>>>(x);
    transpose_split_kernel<<<dim3(N3H / 32, HH / 32), dim3(32, 8)>>>(W_in, 0, HH, N3H);
    transpose_split_kernel<<<dim3(HH / 32, HH / 32), dim3(32, 8)>>>(W_out, 1, HH, HH);

    // GEMM1: BCx = x @ W_in   (16384x2048 @ 2048x6144)
    gemm_mma_kernel<<<dim3(N3H / 128, MROWS / 128), 256>>>(0, nullptr);

    // gate + conv + gate -> y (split fp16)
    conv_kernel<<<dim3(HH / 256, TT / CONV_CHUNK, BB), 256>>>(mask, conv_w);

    // GEMM2: out = y @ W_out  (16384x2048 @ 2048x2048)
    gemm_mma_kernel<<<dim3(HH / 128, MROWS / 128), 256>>>(1, out);
}